// round 4
// baseline (speedup 1.0000x reference)
#include <cuda_runtime.h>
#include <cuda_fp16.h>
#include <cstdint>

// Problem sizes
static constexpr int NTOK = 8192;
static constexpr int DM   = 1024;
static constexpr int NEXP = 8;
static constexpr int RLO  = 16;
static constexpr int KC   = 1152;   // 1024 + 128 lora-combine columns

// Scratch (device globals; no runtime allocation allowed)
__device__ __half g_xh[(long)NTOK * KC];    // [ x | c ]        (rows: token)
__device__ __half g_wh[(long)DM * KC];      // [ W_base | B^T ] (rows: out dim)
__device__ __half g_ah[128L * DM];          // ah[j][k] = A[e][k][r], j=e*16+r
__device__ float  g_hall[(long)NTOK * 128]; // h for all experts

// ---------------------------------------------------------------------------
// Helpers
// ---------------------------------------------------------------------------
static __device__ __forceinline__ uint32_t smem_u32(const void* p) {
    uint32_t a;
    asm("{ .reg .u64 t; cvta.to.shared.u64 t, %1; cvt.u32.u64 %0, t; }" : "=r"(a) : "l"(p));
    return a;
}

#define CP_ASYNC16(saddr, gptr) \
    asm volatile("cp.async.cg.shared.global [%0], [%1], 16;" :: "r"(saddr), "l"(gptr))
#define CP_COMMIT() asm volatile("cp.async.commit_group;" ::: "memory")
#define CP_WAIT1()  asm volatile("cp.async.wait_group 1;" ::: "memory")

// m16n8k16 fp16 MMA, fp32 accumulate
#define MMA_F16(d, a, b) \
    asm volatile("mma.sync.aligned.m16n8k16.row.col.f32.f16.f16.f32 " \
        "{%0,%1,%2,%3}, {%4,%5,%6,%7}, {%8,%9}, {%0,%1,%2,%3};" \
        : "+f"((d)[0]), "+f"((d)[1]), "+f"((d)[2]), "+f"((d)[3]) \
        : "r"((a)[0]), "r"((a)[1]), "r"((a)[2]), "r"((a)[3]), \
          "r"((b)[0]), "r"((b)[1]))

#define LDMX4(r0, r1, r2, r3, addr) \
    asm volatile("ldmatrix.sync.aligned.m8n8.x4.shared.b16 {%0,%1,%2,%3}, [%4];" \
        : "=r"(r0), "=r"(r1), "=r"(r2), "=r"(r3) : "r"(addr))

// ---------------------------------------------------------------------------
// Fused prep kernel: all fp16 operand staging in one launch.
// Segments by linear index: [x: 8.39M][W: 1.05M][B: 131K][A: 131K]
// ---------------------------------------------------------------------------
static constexpr long NX = (long)NTOK * DM;   // 8388608
static constexpr long NW = (long)DM * DM;     // 1048576
static constexpr long NB = 128L * DM;         // 131072
static constexpr long NA = 128L * DM;         // 131072
static constexpr long NPREP = NX + NW + NB + NA;

__global__ void prep_all_kernel(const float* __restrict__ x,
                                const float* __restrict__ Wb,
                                const float* __restrict__ B,
                                const float* __restrict__ A) {
    long i = (long)blockIdx.x * blockDim.x + threadIdx.x;
    if (i < NX) {
        long n = i >> 10, d = i & 1023;
        g_xh[n * KC + d] = __float2half_rn(x[i]);
        return;
    }
    i -= NX;
    if (i < NW) {
        long n = i >> 10, k = i & 1023;
        g_wh[n * KC + k] = __float2half_rn(Wb[i]);
        return;
    }
    i -= NW;
    if (i < NB) {
        int j = (int)(i >> 10), d = (int)(i & 1023);
        g_wh[(long)d * KC + 1024 + j] = __float2half_rn(B[i]);
        return;
    }
    i -= NB;
    if (i < NA) {
        int j = (int)(i >> 10), k = (int)(i & 1023);
        int e = j >> 4, r = j & 15;
        g_ah[(long)j * DM + k] = __float2half_rn(A[((long)e * DM + k) * RLO + r]);
    }
}

// ---------------------------------------------------------------------------
// Gating + lora-combine assembly (fp32 math, one warp per token)
// ---------------------------------------------------------------------------
__global__ void __launch_bounds__(256) gate_c_kernel(const float* __restrict__ x,
                                                     const float* __restrict__ Wg) {
    int warp = (blockIdx.x * blockDim.x + threadIdx.x) >> 5;
    int lane = threadIdx.x & 31;
    if (warp >= NTOK) return;
    const float* xr = x + (long)warp * DM;

    float acc[NEXP];
#pragma unroll
    for (int e = 0; e < NEXP; e++) acc[e] = 0.f;
    for (int d = lane; d < DM; d += 32) {
        float xv = xr[d];
#pragma unroll
        for (int e = 0; e < NEXP; e++) acc[e] = fmaf(xv, Wg[e * DM + d], acc[e]);
    }
#pragma unroll
    for (int e = 0; e < NEXP; e++)
#pragma unroll
        for (int s = 16; s > 0; s >>= 1) acc[e] += __shfl_xor_sync(0xFFFFFFFFu, acc[e], s);

    float v0 = -1e30f; int e0 = 0;
#pragma unroll
    for (int e = 0; e < NEXP; e++) if (acc[e] > v0) { v0 = acc[e]; e0 = e; }
    float v1 = -1e30f; int e1 = 0;
#pragma unroll
    for (int e = 0; e < NEXP; e++) if (e != e0 && acc[e] > v1) { v1 = acc[e]; e1 = e; }
    float b  = expf(v1 - v0);
    float w0 = 1.f / (1.f + b);
    float w1 = b * w0;

    __half* cp = g_xh + (long)warp * KC + 1024;
    for (int i = lane; i < 128; i += 32) cp[i] = __float2half_rn(0.f);
    __syncwarp();
    {
        int j = lane >> 4;
        int r = lane & 15;
        int e = j ? e1 : e0;
        float w = j ? w1 : w0;
        float h = g_hall[(long)warp * 128 + e * RLO + r];
        cp[e * RLO + r] = __float2half_rn(w * h);
    }
}

// ---------------------------------------------------------------------------
// FP16 GEMM: C[m0+128, n0+128] = A[m,:K] * B[n,:K]^T (+bias), fp32 accum.
// 3-stage cp.async ring, ONE __syncthreads per K-tile, ldmatrix fragments.
// 128x128x64 tiles, 8 warps, warp tile 64x32.
// ---------------------------------------------------------------------------
static constexpr int LDH = 72;                          // row pad: 64+8 halves
static constexpr int STAGE_HALFS = 2 * 128 * LDH;       // A + B per stage
static constexpr int STAGE_BYTES = STAGE_HALFS * 2;     // 36864
static constexpr int NSTAGE = 3;
static constexpr int SMEM_BYTES = NSTAGE * STAGE_BYTES; // 110592

template <int BIAS>
__global__ void __launch_bounds__(256, 2)
gemm_f16(const __half* __restrict__ A, long lda,
         const __half* __restrict__ Bm, long ldb,
         float* __restrict__ C, long ldc,
         const float* __restrict__ bias, int ktiles) {
    extern __shared__ __align__(16) __half smem[];

    const int tid  = threadIdx.x;
    const int wid  = tid >> 5;
    const int lane = tid & 31;
    const int wm   = wid >> 2;        // 0..1  (64-row half)
    const int wn   = wid & 3;         // 0..3  (32-col quarter)
    const int g    = lane >> 2;       // 0..7
    const int t4   = lane & 3;        // 0..3
    const int m0   = blockIdx.x * 128;
    const int n0   = blockIdx.y * 128;

    const uint32_t sbase = smem_u32(smem);
    const __half* Ab = A + (long)m0 * lda;
    const __half* Bb = Bm + (long)n0 * ldb;

    // cp.async store addresses (per-thread fixed part)
    const int ldrow = tid >> 3;            // 0..31 base row (+32 per c-iter... see loop)
    const int ldq   = tid & 7;             // 16B chunk in row
    (void)ldrow; (void)ldq;

    auto load_stage = [&](int kt, int stg) {
        const uint32_t sa = sbase + (uint32_t)stg * STAGE_BYTES;
        const uint32_t sb = sa + 128 * LDH * 2;
        const __half* Asrc = Ab + (long)kt * 64;
        const __half* Bsrc = Bb + (long)kt * 64;
#pragma unroll
        for (int c = 0; c < 4; c++) {
            int idx = c * 256 + tid;
            int row = idx >> 3, q = idx & 7;
            CP_ASYNC16(sa + (uint32_t)(row * LDH + q * 8) * 2,
                       Asrc + (long)row * lda + q * 8);
            CP_ASYNC16(sb + (uint32_t)(row * LDH + q * 8) * 2,
                       Bsrc + (long)row * ldb + q * 8);
        }
        CP_COMMIT();
    };

    // ldmatrix per-lane addressing: row = base + (lane&15), col-half = (lane>>4)*8
    const int lrow = lane & 15;
    const int lcol = (lane >> 4) * 8;
    // A fragment base (halves offset within stage): row block wm*64 + i*16
    const uint32_t aoffh = (uint32_t)((wm * 64 + lrow) * LDH + lcol);
    // B fragment base: B region starts at 128*LDH halves; n block wn*32 + jp*16
    const uint32_t boffh = (uint32_t)(128 * LDH + (wn * 32 + lrow) * LDH + lcol);

    float acc[4][4][4];
#pragma unroll
    for (int i = 0; i < 4; i++)
#pragma unroll
        for (int j = 0; j < 4; j++)
#pragma unroll
            for (int r = 0; r < 4; r++) acc[i][j][r] = 0.f;

    load_stage(0, 0);
    load_stage(1, 1);

    int stg = 0;
    for (int kt = 0; kt < ktiles; kt++) {
        CP_WAIT1();                 // stage kt arrived (stage kt+1 may be in flight)
        __syncthreads();            // visibility + WAR: all warps done with slot being reloaded
        if (kt + 2 < ktiles) {
            int s2 = stg + 2; if (s2 >= NSTAGE) s2 -= NSTAGE;
            load_stage(kt + 2, s2);
        } else {
            CP_COMMIT();            // keep group counting aligned
        }

        const uint32_t sa = sbase + (uint32_t)stg * STAGE_BYTES;
#pragma unroll
        for (int ks = 0; ks < 4; ks++) {     // four k16 steps
            const uint32_t ksh = (uint32_t)(ks * 16) * 2;  // byte offset of k16 block
            uint32_t a[4][4];
#pragma unroll
            for (int i = 0; i < 4; i++)
                LDMX4(a[i][0], a[i][1], a[i][2], a[i][3],
                      sa + (aoffh + (uint32_t)(i * 16) * LDH) * 2 + ksh);
            uint32_t b[4][2];
#pragma unroll
            for (int jp = 0; jp < 2; jp++)   // each x4 covers two j-blocks (16 n-rows)
                LDMX4(b[jp * 2][0], b[jp * 2 + 1][0], b[jp * 2][1], b[jp * 2 + 1][1],
                      sa + (boffh + (uint32_t)(jp * 16) * LDH) * 2 + ksh);
#pragma unroll
            for (int i = 0; i < 4; i++)
#pragma unroll
                for (int j = 0; j < 4; j++)
                    MMA_F16(acc[i][j], a[i], b[j]);
        }
        if (++stg == NSTAGE) stg = 0;
    }

    // Epilogue
#pragma unroll
    for (int i = 0; i < 4; i++) {
        int row0 = m0 + wm * 64 + i * 16 + g;
#pragma unroll
        for (int j = 0; j < 4; j++) {
            int col = n0 + wn * 32 + j * 8 + 2 * t4;
            float bx = 0.f, by = 0.f;
            if (BIAS) { bx = bias[col]; by = bias[col + 1]; }
            float2 v0 = { acc[i][j][0] + bx, acc[i][j][1] + by };
            float2 v1 = { acc[i][j][2] + bx, acc[i][j][3] + by };
            *(float2*)(C + (long)row0 * ldc + col)       = v0;
            *(float2*)(C + (long)(row0 + 8) * ldc + col) = v1;
        }
    }
}

// ---------------------------------------------------------------------------
// Launch
// ---------------------------------------------------------------------------
extern "C" void kernel_launch(void* const* d_in, const int* in_sizes, int n_in,
                              void* d_out, int out_size) {
    const float* x    = (const float*)d_in[0];
    const float* Wg   = (const float*)d_in[1];
    const float* A    = (const float*)d_in[2];
    const float* B    = (const float*)d_in[3];
    const float* Wb   = (const float*)d_in[4];
    const float* bias = (const float*)d_in[5];
    float* out = (float*)d_out;

    static bool attr_done = false;
    if (!attr_done) {
        cudaFuncSetAttribute(gemm_f16<0>, cudaFuncAttributeMaxDynamicSharedMemorySize, SMEM_BYTES);
        cudaFuncSetAttribute(gemm_f16<1>, cudaFuncAttributeMaxDynamicSharedMemorySize, SMEM_BYTES);
        attr_done = true;
    }

    __half *xh, *wh, *ah;
    float* hall;
    cudaGetSymbolAddress((void**)&xh, g_xh);
    cudaGetSymbolAddress((void**)&wh, g_wh);
    cudaGetSymbolAddress((void**)&ah, g_ah);
    cudaGetSymbolAddress((void**)&hall, g_hall);

    // 1) fp16 operand staging (single launch)
    prep_all_kernel<<<(int)((NPREP + 255) / 256), 256>>>(x, Wb, B, A);

    // 2) h = x @ A for all experts  (8192 x 128 x 1024)
    gemm_f16<0><<<dim3(NTOK / 128, 1), 256, SMEM_BYTES>>>(
        xh, KC, ah, DM, hall, 128, nullptr, DM / 64);

    // 3) gating + combine coefficients into g_xh tail columns
    gate_c_kernel<<<(NTOK * 32) / 256, 256>>>(x, Wg);

    // 4) fused output GEMM: out = [x|c] @ [W|Bt]^T + bias  (8192 x 1024 x 1152)
    gemm_f16<1><<<dim3(NTOK / 128, DM / 128), 256, SMEM_BYTES>>>(
        xh, KC, wh, KC, out, DM, bias, KC / 64);
}

// round 6
// speedup vs baseline: 1.0743x; 1.0743x over previous
#include <cuda_runtime.h>
#include <cuda_fp16.h>
#include <cstdint>

// Problem sizes
static constexpr int NTOK = 8192;
static constexpr int DM   = 1024;
static constexpr int NEXP = 8;
static constexpr int RLO  = 16;
static constexpr int KC   = 1152;   // 1024 + 128 lora-combine columns

// Scratch (device globals; no runtime allocation allowed)
__device__ __half g_xh[(long)NTOK * KC];    // [ x | c ]        (rows: token)
__device__ __half g_wh[(long)DM * KC];      // [ W_base | B^T ] (rows: out dim)
__device__ __half g_ah[128L * DM];          // ah[j][k] = A[e][k][r], j=e*16+r
__device__ float  g_hall[(long)NTOK * 128]; // h for all experts

// ---------------------------------------------------------------------------
// Helpers
// ---------------------------------------------------------------------------
static __device__ __forceinline__ uint32_t smem_u32(const void* p) {
    uint32_t a;
    asm("{ .reg .u64 t; cvta.to.shared.u64 t, %1; cvt.u32.u64 %0, t; }" : "=r"(a) : "l"(p));
    return a;
}

#define CP_ASYNC16(saddr, gptr) \
    asm volatile("cp.async.cg.shared.global [%0], [%1], 16;" :: "r"(saddr), "l"(gptr))
#define CP_COMMIT() asm volatile("cp.async.commit_group;" ::: "memory")
#define CP_WAIT1()  asm volatile("cp.async.wait_group 1;" ::: "memory")

// m16n8k16 fp16 MMA, fp32 accumulate
#define MMA_F16(d, a, b) \
    asm volatile("mma.sync.aligned.m16n8k16.row.col.f32.f16.f16.f32 " \
        "{%0,%1,%2,%3}, {%4,%5,%6,%7}, {%8,%9}, {%0,%1,%2,%3};" \
        : "+f"((d)[0]), "+f"((d)[1]), "+f"((d)[2]), "+f"((d)[3]) \
        : "r"((a)[0]), "r"((a)[1]), "r"((a)[2]), "r"((a)[3]), \
          "r"((b)[0]), "r"((b)[1]))

#define LDMX4(r0, r1, r2, r3, addr) \
    asm volatile("ldmatrix.sync.aligned.m8n8.x4.shared.b16 {%0,%1,%2,%3}, [%4];" \
        : "=r"(r0), "=r"(r1), "=r"(r2), "=r"(r3) : "r"(addr))

// ---------------------------------------------------------------------------
// Fused prep kernel: all fp16 operand staging in one launch.
// ---------------------------------------------------------------------------
static constexpr long NX = (long)NTOK * DM;   // 8388608
static constexpr long NW = (long)DM * DM;     // 1048576
static constexpr long NB = 128L * DM;         // 131072
static constexpr long NA = 128L * DM;         // 131072
static constexpr long NPREP = NX + NW + NB + NA;

__global__ void prep_all_kernel(const float* __restrict__ x,
                                const float* __restrict__ Wb,
                                const float* __restrict__ B,
                                const float* __restrict__ A) {
    long i = (long)blockIdx.x * blockDim.x + threadIdx.x;
    if (i < NX) {
        long n = i >> 10, d = i & 1023;
        g_xh[n * KC + d] = __float2half_rn(x[i]);
        return;
    }
    i -= NX;
    if (i < NW) {
        long n = i >> 10, k = i & 1023;
        g_wh[n * KC + k] = __float2half_rn(Wb[i]);
        return;
    }
    i -= NW;
    if (i < NB) {
        int j = (int)(i >> 10), d = (int)(i & 1023);
        g_wh[(long)d * KC + 1024 + j] = __float2half_rn(B[i]);
        return;
    }
    i -= NB;
    if (i < NA) {
        int j = (int)(i >> 10), k = (int)(i & 1023);
        int e = j >> 4, r = j & 15;
        g_ah[(long)j * DM + k] = __float2half_rn(A[((long)e * DM + k) * RLO + r]);
    }
}

// ---------------------------------------------------------------------------
// Gating + lora-combine assembly (fp32 math, one warp per token)
// ---------------------------------------------------------------------------
__global__ void __launch_bounds__(256) gate_c_kernel(const float* __restrict__ x,
                                                     const float* __restrict__ Wg) {
    int warp = (blockIdx.x * blockDim.x + threadIdx.x) >> 5;
    int lane = threadIdx.x & 31;
    if (warp >= NTOK) return;
    const float* xr = x + (long)warp * DM;

    float acc[NEXP];
#pragma unroll
    for (int e = 0; e < NEXP; e++) acc[e] = 0.f;
    for (int d = lane; d < DM; d += 32) {
        float xv = xr[d];
#pragma unroll
        for (int e = 0; e < NEXP; e++) acc[e] = fmaf(xv, Wg[e * DM + d], acc[e]);
    }
#pragma unroll
    for (int e = 0; e < NEXP; e++)
#pragma unroll
        for (int s = 16; s > 0; s >>= 1) acc[e] += __shfl_xor_sync(0xFFFFFFFFu, acc[e], s);

    float v0 = -1e30f; int e0 = 0;
#pragma unroll
    for (int e = 0; e < NEXP; e++) if (acc[e] > v0) { v0 = acc[e]; e0 = e; }
    float v1 = -1e30f; int e1 = 0;
#pragma unroll
    for (int e = 0; e < NEXP; e++) if (e != e0 && acc[e] > v1) { v1 = acc[e]; e1 = e; }
    float b  = expf(v1 - v0);
    float w0 = 1.f / (1.f + b);
    float w1 = b * w0;

    __half* cp = g_xh + (long)warp * KC + 1024;
    for (int i = lane; i < 128; i += 32) cp[i] = __float2half_rn(0.f);
    __syncwarp();
    {
        int j = lane >> 4;
        int r = lane & 15;
        int e = j ? e1 : e0;
        float w = j ? w1 : w0;
        float h = g_hall[(long)warp * 128 + e * RLO + r];
        cp[e * RLO + r] = __float2half_rn(w * h);
    }
}

// ---------------------------------------------------------------------------
// FP16 GEMM: C[m0+BM, n0+128] = A[m,:K] * B[n,:K]^T (+bias), fp32 accum.
// BM = MI*32. 8 warps (2 x 4), warp tile (MI*16) x 32. 3-stage cp.async ring,
// 1 sync/ktile, ldmatrix fragments. A-fragments double-buffered across the
// four k16 steps; B-fragments double-buffered only for MI<=2 (reg budget).
// ---------------------------------------------------------------------------
static constexpr int LDH = 72;                          // row pad: 64+8 halves
static constexpr int NSTAGE = 3;

template <int MI, int BIAS>
__global__ void __launch_bounds__(256, 2)
gemm_f16(const __half* __restrict__ A, long lda,
         const __half* __restrict__ Bm, long ldb,
         float* __restrict__ C, long ldc,
         const float* __restrict__ bias, int ktiles) {
    constexpr int BM = MI * 32;
    constexpr int STAGE_HALFS = (BM + 128) * LDH;
    constexpr int STAGE_BYTES = STAGE_HALFS * 2;
    constexpr int BBUF = (MI <= 2) ? 2 : 1;             // b-frag buffers

    extern __shared__ __align__(16) __half smem[];

    const int tid  = threadIdx.x;
    const int wid  = tid >> 5;
    const int lane = tid & 31;
    const int wm   = wid >> 2;        // 0..1
    const int wn   = wid & 3;         // 0..3
    const int g    = lane >> 2;       // 0..7
    const int t4   = lane & 3;        // 0..3
    const int m0   = blockIdx.x * BM;
    const int n0   = blockIdx.y * 128;

    const uint32_t sbase = smem_u32(smem);
    const __half* Ab = A + (long)m0 * lda;
    const __half* Bb = Bm + (long)n0 * ldb;

    auto load_stage = [&](int kt, int stg) {
        const uint32_t sa = sbase + (uint32_t)stg * STAGE_BYTES;
        const uint32_t sb = sa + BM * LDH * 2;
        const __half* Asrc = Ab + (long)kt * 64;
        const __half* Bsrc = Bb + (long)kt * 64;
#pragma unroll
        for (int c = 0; c < BM * 8 / 256; c++) {
            int idx = c * 256 + tid;
            int row = idx >> 3, q = idx & 7;
            CP_ASYNC16(sa + (uint32_t)(row * LDH + q * 8) * 2,
                       Asrc + (long)row * lda + q * 8);
        }
#pragma unroll
        for (int c = 0; c < 4; c++) {
            int idx = c * 256 + tid;
            int row = idx >> 3, q = idx & 7;
            CP_ASYNC16(sb + (uint32_t)(row * LDH + q * 8) * 2,
                       Bsrc + (long)row * ldb + q * 8);
        }
        CP_COMMIT();
    };

    // ldmatrix per-lane addressing
    const int lrow = lane & 15;
    const int lcol = (lane >> 4) * 8;
    const uint32_t aoffh = (uint32_t)((wm * (MI * 16) + lrow) * LDH + lcol);
    const uint32_t boffh = (uint32_t)(BM * LDH + (wn * 32 + lrow) * LDH + lcol);

    float acc[MI][4][4];
#pragma unroll
    for (int i = 0; i < MI; i++)
#pragma unroll
        for (int j = 0; j < 4; j++)
#pragma unroll
            for (int r = 0; r < 4; r++) acc[i][j][r] = 0.f;

    load_stage(0, 0);
    load_stage(1, 1);

    int stg = 0;
    for (int kt = 0; kt < ktiles; kt++) {
        CP_WAIT1();
        __syncthreads();
        if (kt + 2 < ktiles) {
            int s2 = stg + 2; if (s2 >= NSTAGE) s2 -= NSTAGE;
            load_stage(kt + 2, s2);
        } else {
            CP_COMMIT();
        }

        const uint32_t sa = sbase + (uint32_t)stg * STAGE_BYTES;

        uint32_t a[2][MI][4], b[BBUF][4][2];
        auto ldfrag_a = [&](int ks, int buf) {
            const uint32_t ksh = (uint32_t)(ks * 16) * 2;
#pragma unroll
            for (int i = 0; i < MI; i++)
                LDMX4(a[buf][i][0], a[buf][i][1], a[buf][i][2], a[buf][i][3],
                      sa + (aoffh + (uint32_t)(i * 16) * LDH) * 2 + ksh);
        };
        auto ldfrag_b = [&](int ks, int buf) {
            const uint32_t ksh = (uint32_t)(ks * 16) * 2;
#pragma unroll
            for (int jp = 0; jp < 2; jp++)
                LDMX4(b[buf][jp * 2][0], b[buf][jp * 2 + 1][0],
                      b[buf][jp * 2][1], b[buf][jp * 2 + 1][1],
                      sa + (boffh + (uint32_t)(jp * 16) * LDH) * 2 + ksh);
        };

        ldfrag_a(0, 0);
        ldfrag_b(0, 0);
#pragma unroll
        for (int ks = 0; ks < 4; ks++) {
            const int cur = ks & 1;
            const int acur = cur;
            const int bcur = (BBUF == 2) ? cur : 0;
            if (ks < 3) {
                ldfrag_a(ks + 1, acur ^ 1);
                if (BBUF == 2) ldfrag_b(ks + 1, bcur ^ 1);
            }
#pragma unroll
            for (int i = 0; i < MI; i++)
#pragma unroll
                for (int j = 0; j < 4; j++)
                    MMA_F16(acc[i][j], a[acur][i], b[bcur][j]);
            if (BBUF == 1 && ks < 3) ldfrag_b(ks + 1, 0);
        }
        if (++stg == NSTAGE) stg = 0;
    }

    // Epilogue
#pragma unroll
    for (int i = 0; i < MI; i++) {
        int row0 = m0 + wm * (MI * 16) + i * 16 + g;
#pragma unroll
        for (int j = 0; j < 4; j++) {
            int col = n0 + wn * 32 + j * 8 + 2 * t4;
            float bx = 0.f, by = 0.f;
            if (BIAS) { bx = bias[col]; by = bias[col + 1]; }
            float2 v0 = { acc[i][j][0] + bx, acc[i][j][1] + by };
            float2 v1 = { acc[i][j][2] + bx, acc[i][j][3] + by };
            *(float2*)(C + (long)row0 * ldc + col)       = v0;
            *(float2*)(C + (long)(row0 + 8) * ldc + col) = v1;
        }
    }
}

static constexpr int SMEM_BYTES_128 = NSTAGE * (128 + 128) * LDH * 2; // 110592
static constexpr int SMEM_BYTES_64  = NSTAGE * (64 + 128) * LDH * 2;  // 82944

// ---------------------------------------------------------------------------
// Launch
// ---------------------------------------------------------------------------
extern "C" void kernel_launch(void* const* d_in, const int* in_sizes, int n_in,
                              void* d_out, int out_size) {
    const float* x    = (const float*)d_in[0];
    const float* Wg   = (const float*)d_in[1];
    const float* A    = (const float*)d_in[2];
    const float* B    = (const float*)d_in[3];
    const float* Wb   = (const float*)d_in[4];
    const float* bias = (const float*)d_in[5];
    float* out = (float*)d_out;

    static bool attr_done = false;
    if (!attr_done) {
        cudaFuncSetAttribute(gemm_f16<2, 0>, cudaFuncAttributeMaxDynamicSharedMemorySize, SMEM_BYTES_64);
        cudaFuncSetAttribute(gemm_f16<4, 1>, cudaFuncAttributeMaxDynamicSharedMemorySize, SMEM_BYTES_128);
        attr_done = true;
    }

    __half *xh, *wh, *ah;
    float* hall;
    cudaGetSymbolAddress((void**)&xh, g_xh);
    cudaGetSymbolAddress((void**)&wh, g_wh);
    cudaGetSymbolAddress((void**)&ah, g_ah);
    cudaGetSymbolAddress((void**)&hall, g_hall);

    // 1) fp16 operand staging (single launch)
    prep_all_kernel<<<(int)((NPREP + 255) / 256), 256>>>(x, Wb, B, A);

    // 2) h = x @ A for all experts  (8192 x 128 x 1024), BM=64 -> 128 CTAs
    gemm_f16<2, 0><<<dim3(NTOK / 64, 1), 256, SMEM_BYTES_64>>>(
        xh, KC, ah, DM, hall, 128, nullptr, DM / 64);

    // 3) gating + combine coefficients into g_xh tail columns
    gate_c_kernel<<<(NTOK * 32) / 256, 256>>>(x, Wg);

    // 4) fused output GEMM: out = [x|c] @ [W|Bt]^T + bias  (8192 x 1024 x 1152)
    gemm_f16<4, 1><<<dim3(NTOK / 128, DM / 128), 256, SMEM_BYTES_128>>>(
        xh, KC, wh, KC, out, DM, bias, KC / 64);
}

// round 7
// speedup vs baseline: 1.1075x; 1.0309x over previous
#include <cuda_runtime.h>
#include <cuda_fp16.h>
#include <cstdint>

// Problem sizes
static constexpr int NTOK = 8192;
static constexpr int DM   = 1024;
static constexpr int NEXP = 8;
static constexpr int RLO  = 16;
static constexpr int KC   = 1152;   // 1024 + 128 lora-combine columns

// Scratch (device globals; no runtime allocation allowed)
__device__ __half g_xh[(long)NTOK * KC];    // [ x | c ]        (rows: token)
__device__ __half g_wh[(long)DM * KC];      // [ W_base | B^T ] (rows: out dim)
__device__ __half g_ah[128L * DM];          // ah[j][k] = A[e][k][r], j=e*16+r
__device__ float  g_hall[(long)NTOK * 128]; // h for all experts

// ---------------------------------------------------------------------------
// Helpers
// ---------------------------------------------------------------------------
static __device__ __forceinline__ uint32_t smem_u32(const void* p) {
    uint32_t a;
    asm("{ .reg .u64 t; cvta.to.shared.u64 t, %1; cvt.u32.u64 %0, t; }" : "=r"(a) : "l"(p));
    return a;
}

#define CP_ASYNC16(saddr, gptr) \
    asm volatile("cp.async.cg.shared.global [%0], [%1], 16;" :: "r"(saddr), "l"(gptr))
#define CP_COMMIT() asm volatile("cp.async.commit_group;" ::: "memory")
#define CP_WAIT1()  asm volatile("cp.async.wait_group 1;" ::: "memory")

// m16n8k16 fp16 MMA, fp32 accumulate
#define MMA_F16(d, a, b) \
    asm volatile("mma.sync.aligned.m16n8k16.row.col.f32.f16.f16.f32 " \
        "{%0,%1,%2,%3}, {%4,%5,%6,%7}, {%8,%9}, {%0,%1,%2,%3};" \
        : "+f"((d)[0]), "+f"((d)[1]), "+f"((d)[2]), "+f"((d)[3]) \
        : "r"((a)[0]), "r"((a)[1]), "r"((a)[2]), "r"((a)[3]), \
          "r"((b)[0]), "r"((b)[1]))

#define LDMX4(r0, r1, r2, r3, addr) \
    asm volatile("ldmatrix.sync.aligned.m8n8.x4.shared.b16 {%0,%1,%2,%3}, [%4];" \
        : "=r"(r0), "=r"(r1), "=r"(r2), "=r"(r3) : "r"(addr))

// ---------------------------------------------------------------------------
// Fused prep kernel: all fp16 operand staging in one launch.
// ---------------------------------------------------------------------------
static constexpr long NX = (long)NTOK * DM;   // 8388608
static constexpr long NW = (long)DM * DM;     // 1048576
static constexpr long NB = 128L * DM;         // 131072
static constexpr long NA = 128L * DM;         // 131072
static constexpr long NPREP = NX + NW + NB + NA;

__global__ void prep_all_kernel(const float* __restrict__ x,
                                const float* __restrict__ Wb,
                                const float* __restrict__ B,
                                const float* __restrict__ A) {
    long i = (long)blockIdx.x * blockDim.x + threadIdx.x;
    if (i < NX) {
        long n = i >> 10, d = i & 1023;
        g_xh[n * KC + d] = __float2half_rn(x[i]);
        return;
    }
    i -= NX;
    if (i < NW) {
        long n = i >> 10, k = i & 1023;
        g_wh[n * KC + k] = __float2half_rn(Wb[i]);
        return;
    }
    i -= NW;
    if (i < NB) {
        int j = (int)(i >> 10), d = (int)(i & 1023);
        g_wh[(long)d * KC + 1024 + j] = __float2half_rn(B[i]);
        return;
    }
    i -= NB;
    if (i < NA) {
        int j = (int)(i >> 10), k = (int)(i & 1023);
        int e = j >> 4, r = j & 15;
        g_ah[(long)j * DM + k] = __float2half_rn(A[((long)e * DM + k) * RLO + r]);
    }
}

// ---------------------------------------------------------------------------
// Gating + lora-combine assembly (fp32 math, one warp per token)
// ---------------------------------------------------------------------------
__global__ void __launch_bounds__(256) gate_c_kernel(const float* __restrict__ x,
                                                     const float* __restrict__ Wg) {
    int warp = (blockIdx.x * blockDim.x + threadIdx.x) >> 5;
    int lane = threadIdx.x & 31;
    if (warp >= NTOK) return;
    const float* xr = x + (long)warp * DM;

    float acc[NEXP];
#pragma unroll
    for (int e = 0; e < NEXP; e++) acc[e] = 0.f;
    for (int d = lane; d < DM; d += 32) {
        float xv = xr[d];
#pragma unroll
        for (int e = 0; e < NEXP; e++) acc[e] = fmaf(xv, Wg[e * DM + d], acc[e]);
    }
#pragma unroll
    for (int e = 0; e < NEXP; e++)
#pragma unroll
        for (int s = 16; s > 0; s >>= 1) acc[e] += __shfl_xor_sync(0xFFFFFFFFu, acc[e], s);

    float v0 = -1e30f; int e0 = 0;
#pragma unroll
    for (int e = 0; e < NEXP; e++) if (acc[e] > v0) { v0 = acc[e]; e0 = e; }
    float v1 = -1e30f; int e1 = 0;
#pragma unroll
    for (int e = 0; e < NEXP; e++) if (e != e0 && acc[e] > v1) { v1 = acc[e]; e1 = e; }
    float b  = expf(v1 - v0);
    float w0 = 1.f / (1.f + b);
    float w1 = b * w0;

    __half* cp = g_xh + (long)warp * KC + 1024;
    for (int i = lane; i < 128; i += 32) cp[i] = __float2half_rn(0.f);
    __syncwarp();
    {
        int j = lane >> 4;
        int r = lane & 15;
        int e = j ? e1 : e0;
        float w = j ? w1 : w0;
        float h = g_hall[(long)warp * 128 + e * RLO + r];
        cp[e * RLO + r] = __float2half_rn(w * h);
    }
}

// ---------------------------------------------------------------------------
// FP16 GEMM: C[m0+BM, n0+BN] = A[m,:K] * B[n,:K]^T (+bias), fp32 accum.
// BM = WM*MI*16, BN = WN*NJ*8. 8 warps (WM x WN), warp tile (MI*16)x(NJ*8).
// 2-stage cp.async, ldmatrix fragments, 3 CTAs/SM (24 warps) for latency hiding.
// ---------------------------------------------------------------------------
static constexpr int LDH = 72;                          // row pad: 64+8 halves
static constexpr int NSTAGE = 2;

template <int WM, int WN, int MI, int NJ, int BIAS>
__global__ void __launch_bounds__(256, 3)
gemm_f16(const __half* __restrict__ A, long lda,
         const __half* __restrict__ Bm, long ldb,
         float* __restrict__ C, long ldc,
         const float* __restrict__ bias, int ktiles) {
    constexpr int BM = WM * MI * 16;
    constexpr int BN = WN * NJ * 8;
    constexpr int STAGE_HALFS = (BM + BN) * LDH;
    constexpr int STAGE_BYTES = STAGE_HALFS * 2;

    extern __shared__ __align__(16) __half smem[];

    const int tid  = threadIdx.x;
    const int wid  = tid >> 5;
    const int lane = tid & 31;
    const int wm   = wid / WN;
    const int wn   = wid % WN;
    const int g    = lane >> 2;       // 0..7
    const int t4   = lane & 3;        // 0..3
    const int m0   = blockIdx.x * BM;
    const int n0   = blockIdx.y * BN;

    const uint32_t sbase = smem_u32(smem);
    const __half* Ab = A + (long)m0 * lda;
    const __half* Bb = Bm + (long)n0 * ldb;

    auto load_stage = [&](int kt, int stg) {
        const uint32_t sa = sbase + (uint32_t)stg * STAGE_BYTES;
        const uint32_t sb = sa + BM * LDH * 2;
        const __half* Asrc = Ab + (long)kt * 64;
        const __half* Bsrc = Bb + (long)kt * 64;
#pragma unroll
        for (int c = 0; c < BM * 8 / 256; c++) {
            int idx = c * 256 + tid;
            int row = idx >> 3, q = idx & 7;
            CP_ASYNC16(sa + (uint32_t)(row * LDH + q * 8) * 2,
                       Asrc + (long)row * lda + q * 8);
        }
#pragma unroll
        for (int c = 0; c < BN * 8 / 256; c++) {
            int idx = c * 256 + tid;
            int row = idx >> 3, q = idx & 7;
            CP_ASYNC16(sb + (uint32_t)(row * LDH + q * 8) * 2,
                       Bsrc + (long)row * ldb + q * 8);
        }
        CP_COMMIT();
    };

    // ldmatrix per-lane addressing
    const int lrow = lane & 15;
    const int lcol = (lane >> 4) * 8;
    const uint32_t aoffh = (uint32_t)((wm * (MI * 16) + lrow) * LDH + lcol);
    const uint32_t boffh = (uint32_t)(BM * LDH + (wn * (NJ * 8) + lrow) * LDH + lcol);

    float acc[MI][NJ][4];
#pragma unroll
    for (int i = 0; i < MI; i++)
#pragma unroll
        for (int j = 0; j < NJ; j++)
#pragma unroll
            for (int r = 0; r < 4; r++) acc[i][j][r] = 0.f;

    load_stage(0, 0);

    for (int kt = 0; kt < ktiles; kt++) {
        if (kt + 1 < ktiles) load_stage(kt + 1, (kt + 1) & 1);
        else CP_COMMIT();
        CP_WAIT1();
        __syncthreads();

        const uint32_t sa = sbase + (uint32_t)(kt & 1) * STAGE_BYTES;
#pragma unroll
        for (int ks = 0; ks < 4; ks++) {
            const uint32_t ksh = (uint32_t)(ks * 16) * 2;
            uint32_t a[MI][4];
#pragma unroll
            for (int i = 0; i < MI; i++)
                LDMX4(a[i][0], a[i][1], a[i][2], a[i][3],
                      sa + (aoffh + (uint32_t)(i * 16) * LDH) * 2 + ksh);
            uint32_t b[NJ][2];
#pragma unroll
            for (int jp = 0; jp < NJ / 2; jp++)
                LDMX4(b[jp * 2][0], b[jp * 2 + 1][0], b[jp * 2][1], b[jp * 2 + 1][1],
                      sa + (boffh + (uint32_t)(jp * 16) * LDH) * 2 + ksh);
#pragma unroll
            for (int i = 0; i < MI; i++)
#pragma unroll
                for (int j = 0; j < NJ; j++)
                    MMA_F16(acc[i][j], a[i], b[j]);
        }
        __syncthreads();
    }

    // Epilogue
#pragma unroll
    for (int i = 0; i < MI; i++) {
        int row0 = m0 + wm * (MI * 16) + i * 16 + g;
#pragma unroll
        for (int j = 0; j < NJ; j++) {
            int col = n0 + wn * (NJ * 8) + j * 8 + 2 * t4;
            float bx = 0.f, by = 0.f;
            if (BIAS) { bx = bias[col]; by = bias[col + 1]; }
            float2 v0 = { acc[i][j][0] + bx, acc[i][j][1] + by };
            float2 v1 = { acc[i][j][2] + bx, acc[i][j][3] + by };
            *(float2*)(C + (long)row0 * ldc + col)       = v0;
            *(float2*)(C + (long)(row0 + 8) * ldc + col) = v1;
        }
    }
}

// GEMM<0>: BM=64, BN=128 (WM=2, WN=4, MI=2, NJ=4)
// GEMM<1>: BM=128, BN=64 (WM=4, WN=2, MI=2, NJ=4)
static constexpr int SMEM_B0 = NSTAGE * (64 + 128) * LDH * 2;  // 55296
static constexpr int SMEM_B1 = NSTAGE * (128 + 64) * LDH * 2;  // 55296

// ---------------------------------------------------------------------------
// Launch
// ---------------------------------------------------------------------------
extern "C" void kernel_launch(void* const* d_in, const int* in_sizes, int n_in,
                              void* d_out, int out_size) {
    const float* x    = (const float*)d_in[0];
    const float* Wg   = (const float*)d_in[1];
    const float* A    = (const float*)d_in[2];
    const float* B    = (const float*)d_in[3];
    const float* Wb   = (const float*)d_in[4];
    const float* bias = (const float*)d_in[5];
    float* out = (float*)d_out;

    static bool attr_done = false;
    if (!attr_done) {
        cudaFuncSetAttribute((const void*)gemm_f16<2, 4, 2, 4, 0>,
                             cudaFuncAttributeMaxDynamicSharedMemorySize, SMEM_B0);
        cudaFuncSetAttribute((const void*)gemm_f16<4, 2, 2, 4, 1>,
                             cudaFuncAttributeMaxDynamicSharedMemorySize, SMEM_B1);
        attr_done = true;
    }

    __half *xh, *wh, *ah;
    float* hall;
    cudaGetSymbolAddress((void**)&xh, g_xh);
    cudaGetSymbolAddress((void**)&wh, g_wh);
    cudaGetSymbolAddress((void**)&ah, g_ah);
    cudaGetSymbolAddress((void**)&hall, g_hall);

    // 1) fp16 operand staging (single launch)
    prep_all_kernel<<<(int)((NPREP + 255) / 256), 256>>>(x, Wb, B, A);

    // 2) h = x @ A for all experts  (8192 x 128 x 1024), BM=64 -> 128 CTAs
    gemm_f16<2, 4, 2, 4, 0><<<dim3(NTOK / 64, 1), 256, SMEM_B0>>>(
        xh, KC, ah, DM, hall, 128, nullptr, DM / 64);

    // 3) gating + combine coefficients into g_xh tail columns
    gate_c_kernel<<<(NTOK * 32) / 256, 256>>>(x, Wg);

    // 4) fused output GEMM: out = [x|c] @ [W|Bt]^T + bias  (8192 x 1024 x 1152)
    //    BM=128, BN=64 -> grid (64, 16) = 1024 CTAs, 3 CTAs/SM
    gemm_f16<4, 2, 2, 4, 1><<<dim3(NTOK / 128, DM / 64), 256, SMEM_B1>>>(
        xh, KC, wh, KC, out, DM, bias, KC / 64);
}